// round 17
// baseline (speedup 1.0000x reference)
#include <cuda_runtime.h>
#include <cuda_bf16.h>
#include <math.h>
#include <stdint.h>

#define BATCH   2
#define SEQ     2048
#define DMODEL  1024
#define NHEADS  16
#define DHEAD   64
#define MTOT    (BATCH*SEQ)   // 4096
#define NELEM   (MTOT*DMODEL)

// Scratch (allocation-free rule: __device__ globals)
__device__ float g_A[NELEM];            // tf32-rounded hidden
__device__ float g_Q[NELEM];
__device__ float g_K[NELEM];
__device__ float g_V[NELEM];
__device__ float g_O[NELEM];            // attention output, tf32-pre-rounded
__device__ float g_WT[3072*1024];       // [n][k] tf32-rounded fused Wq|Wk|Wv
__device__ float g_WoT[1024*1024];      // [n][k] tf32-rounded Wo

__device__ __forceinline__ float tf32r(float x) {
    asm("cvt.rna.tf32.f32 %0, %0;" : "+f"(x));
    return x;
}

__device__ __forceinline__ void mma_tf32(float c[4], const unsigned a[4], const unsigned b[2]) {
    asm volatile(
        "mma.sync.aligned.m16n8k8.row.col.f32.tf32.tf32.f32 "
        "{%0,%1,%2,%3}, {%4,%5,%6,%7}, {%8,%9}, {%0,%1,%2,%3};\n"
        : "+f"(c[0]), "+f"(c[1]), "+f"(c[2]), "+f"(c[3])
        : "r"(a[0]), "r"(a[1]), "r"(a[2]), "r"(a[3]), "r"(b[0]), "r"(b[1]));
}
__device__ __forceinline__ void mma_bf16(float c[4], const unsigned a[4], const unsigned b[2]) {
    asm volatile(
        "mma.sync.aligned.m16n8k16.row.col.f32.bf16.bf16.f32 "
        "{%0,%1,%2,%3}, {%4,%5,%6,%7}, {%8,%9}, {%0,%1,%2,%3};\n"
        : "+f"(c[0]), "+f"(c[1]), "+f"(c[2]), "+f"(c[3])
        : "r"(a[0]), "r"(a[1]), "r"(a[2]), "r"(a[3]), "r"(b[0]), "r"(b[1]));
}
__device__ __forceinline__ void ldmx4(unsigned &d0, unsigned &d1, unsigned &d2, unsigned &d3,
                                      uint32_t addr) {
    asm volatile("ldmatrix.sync.aligned.m8n8.x4.shared.b16 {%0,%1,%2,%3}, [%4];"
                 : "=r"(d0), "=r"(d1), "=r"(d2), "=r"(d3) : "r"(addr));
}
__device__ __forceinline__ void ldmx4t(unsigned &d0, unsigned &d1, unsigned &d2, unsigned &d3,
                                       uint32_t addr) {
    asm volatile("ldmatrix.sync.aligned.m8n8.x4.trans.shared.b16 {%0,%1,%2,%3}, [%4];"
                 : "=r"(d0), "=r"(d1), "=r"(d2), "=r"(d3) : "r"(addr));
}
__device__ __forceinline__ void ldmx2(unsigned &d0, unsigned &d1, uint32_t addr) {
    asm volatile("ldmatrix.sync.aligned.m8n8.x2.shared.b16 {%0,%1}, [%2];"
                 : "=r"(d0), "=r"(d1) : "r"(addr));
}
__device__ __forceinline__ unsigned bfpack(float a, float b) {
    __nv_bfloat162 h = __floats2bfloat162_rn(a, b);
    return *reinterpret_cast<unsigned*>(&h);
}
__device__ __forceinline__ void bfsplit2(float a, float b, unsigned &hi, unsigned &lo) {
    float ha = __bfloat162float(__float2bfloat16_rn(a));
    float hb = __bfloat162float(__float2bfloat16_rn(b));
    hi = bfpack(ha, hb);
    lo = bfpack(a - ha, b - hb);
}
__device__ __forceinline__ void cp_async16(uint32_t dst, const void* src) {
    asm volatile("cp.async.cg.shared.global [%0], [%1], 16;" :: "r"(dst), "l"(src));
}

// ---------------------------------------------------------------------------
// prep_round: g_A = tf32r(hidden), float4 per thread.
// ---------------------------------------------------------------------------
__global__ void prep_round(const float* __restrict__ H, float* __restrict__ A)
{
    int i = blockIdx.x * blockDim.x + threadIdx.x;
    float4 v = ((const float4*)H)[i];
    v.x = tf32r(v.x); v.y = tf32r(v.y); v.z = tf32r(v.z); v.w = tf32r(v.w);
    ((float4*)A)[i] = v;
}

// ---------------------------------------------------------------------------
// prep_weights: transpose [k][n] -> [n][k] with tf32 rounding.
// ---------------------------------------------------------------------------
__global__ void prep_weights(const float* __restrict__ Wq, const float* __restrict__ Wk,
                             const float* __restrict__ Wv, const float* __restrict__ Wo,
                             float* __restrict__ WT, float* __restrict__ WoT)
{
    __shared__ float t[32][33];
    int which = blockIdx.z;
    const float* W = (which == 0) ? Wq : (which == 1) ? Wk : (which == 2) ? Wv : Wo;
    int n0 = blockIdx.x * 32, k0 = blockIdx.y * 32;
    #pragma unroll
    for (int i = 0; i < 32; i += 8)
        t[threadIdx.y + i][threadIdx.x] = W[(size_t)(k0 + threadIdx.y + i) * 1024 + n0 + threadIdx.x];
    __syncthreads();
    float* dst = (which < 3) ? (WT + (size_t)which * 1024 * 1024) : WoT;
    #pragma unroll
    for (int i = 0; i < 32; i += 8)
        dst[(size_t)(n0 + threadIdx.y + i) * 1024 + k0 + threadIdx.x] =
            tf32r(t[threadIdx.x][threadIdx.y + i]);
}

// ---------------------------------------------------------------------------
// TF32 GEMM with ldmatrix fragments, pre-rounded operands (R14-proven).
// ---------------------------------------------------------------------------
#define GEMM_SMEM 73728

template<bool QKV>
__global__ __launch_bounds__(256, 2)
void gemm_ldm(const float* __restrict__ A, const float* __restrict__ BT,
              float* __restrict__ C, float* __restrict__ Qo, float* __restrict__ Ko,
              float* __restrict__ Vo, int M, int N, int K)
{
    extern __shared__ float gsm[];

    const int tid  = threadIdx.x;
    const int lane = tid & 31;
    const int warp = tid >> 5;
    const int rowW = (warp >> 2) * 64;
    const int colW = (warp & 3) * 32;
    const int qr   = lane >> 2;
    const int qc   = lane & 3;
    const int lr   = lane & 7;

    const int rowBase = blockIdx.y * 128;
    const int colBase = blockIdx.x * 128;

    const uint32_t sbase = (uint32_t)__cvta_generic_to_shared(gsm);

    const uint32_t aLane = (uint32_t)(((rowW + ((lane >> 3) & 1) * 8 + lr) * 36
                                       + (lane >> 4) * 4) * 4);
    const uint32_t bLane = (uint32_t)(((colW + lr) * 36
                                       + ((lane >> 3) & 1) * 4) * 4) + 18432u;

    const int rS = tid >> 3, cS = (tid & 7) << 2;

    auto stage = [&](int buf, int k0) {
        uint32_t ab  = sbase + (uint32_t)buf * 36864u;
        uint32_t btb = ab + 18432u;
        #pragma unroll
        for (int l = 0; l < 4; l++) {
            int rr = rS + 32 * l;
            cp_async16(ab  + (uint32_t)((rr * 36 + cS) * 4),
                       A  + (size_t)(rowBase + rr) * K + k0 + cS);
            cp_async16(btb + (uint32_t)((rr * 36 + cS) * 4),
                       BT + (size_t)(colBase + rr) * K + k0 + cS);
        }
        asm volatile("cp.async.commit_group;");
    };

    float acc[4][4][4];
    #pragma unroll
    for (int mt = 0; mt < 4; mt++)
        #pragma unroll
        for (int nt = 0; nt < 4; nt++)
            #pragma unroll
            for (int i = 0; i < 4; i++) acc[mt][nt][i] = 0.f;

    stage(0, 0);
    int buf = 0;
    for (int k0 = 0; k0 < K; k0 += 32) {
        asm volatile("cp.async.wait_group 0;");
        __syncthreads();
        if (k0 + 32 < K) stage(buf ^ 1, k0 + 32);

        const uint32_t bb = sbase + (uint32_t)buf * 36864u;

        #pragma unroll
        for (int kk = 0; kk < 4; kk++) {
            unsigned b[4][2];
            #pragma unroll
            for (int nt = 0; nt < 4; nt++)
                ldmx2(b[nt][0], b[nt][1],
                      bb + bLane + (uint32_t)((nt * 8 * 36 + kk * 8) * 4));
            #pragma unroll
            for (int mt = 0; mt < 4; mt++) {
                unsigned a[4];
                ldmx4(a[0], a[1], a[2], a[3],
                      bb + aLane + (uint32_t)((mt * 16 * 36 + kk * 8) * 4));
                #pragma unroll
                for (int nt = 0; nt < 4; nt++)
                    mma_tf32(acc[mt][nt], a, b[nt]);
            }
        }
        buf ^= 1;
    }

    #pragma unroll
    for (int mt = 0; mt < 4; mt++) {
        int r = rowBase + rowW + mt * 16 + qr;
        #pragma unroll
        for (int nt = 0; nt < 4; nt++) {
            int cg = colBase + colW + nt * 8 + 2 * qc;
            float2 v0 = make_float2(acc[mt][nt][0], acc[mt][nt][1]);
            float2 v1 = make_float2(acc[mt][nt][2], acc[mt][nt][3]);
            if (QKV) {
                float* dst; int c;
                if (cg < 1024)      { dst = Qo; c = cg; }
                else if (cg < 2048) { dst = Ko; c = cg - 1024; }
                else                { dst = Vo; c = cg - 2048; }
                *(float2*)(dst + (size_t)r * 1024 + c)       = v0;
                *(float2*)(dst + (size_t)(r + 8) * 1024 + c) = v1;
            } else {
                *(float2*)(C + (size_t)r * N + cg)       = v0;
                *(float2*)(C + (size_t)(r + 8) * N + cg) = v1;
            }
        }
    }
}

// ---------------------------------------------------------------------------
// RoPE in-place (proven).
// ---------------------------------------------------------------------------
__global__ void rope_kernel(float* __restrict__ Q, float* __restrict__ K,
                            const float* __restrict__ cosT,
                            const float* __restrict__ sinT)
{
    int idx = blockIdx.x * blockDim.x + threadIdx.x;
    int d  = idx & 31;
    int h  = (idx >> 5) & (NHEADS - 1);
    int ms = idx >> 9;
    int s  = ms & (SEQ - 1);

    float c  = cosT[s * 32 + d];
    float sn = sinT[s * 32 + d];
    size_t base = (size_t)ms * DMODEL + h * DHEAD + d;

    float x1 = Q[base], x2 = Q[base + 32];
    Q[base]      = x1 * c - x2 * sn;
    Q[base + 32] = x2 * c + x1 * sn;

    float y1 = K[base], y2 = K[base + 32];
    K[base]      = y1 * c - y2 * sn;
    K[base + 32] = y2 * c + y1 * sn;
}

// ---------------------------------------------------------------------------
// Flash attention: bf16 3-term split, 64 q-rows, 4 warps.
//  - K fragments: ONE ldmatrix.x4 covering KH (mats 0,1) + KL (mats 2,3)
//  - P fragments: built entirely in registers from the QK^T accumulators
//    (s[nt] layout == PV A-fragment layout); no P smem, one less sync
//  - V fragments: ONE ldmatrix.x4.trans covering VH + VL
// Smem: KH[64][72] @0, KL @9216B, VH @18432B, VL @27648B = 36864 B.
// ---------------------------------------------------------------------------
#define ATTN_SMEM (4 * 4608 * 2)

__global__ __launch_bounds__(128, 4)
void attn_mma(const float* __restrict__ Q, const float* __restrict__ K,
              const float* __restrict__ V, float* __restrict__ O)
{
    extern __shared__ __nv_bfloat16 smb[];
    __nv_bfloat16* KH = smb;               // [64][72]
    __nv_bfloat16* KL = smb + 4608;
    __nv_bfloat16* VH = smb + 2 * 4608;
    __nv_bfloat16* VL = smb + 3 * 4608;

    const uint32_t smemB = (uint32_t)__cvta_generic_to_shared(smb);

    const int qb = blockIdx.x, h = blockIdx.y, b = blockIdx.z;
    const int tid = threadIdx.x;
    const int lane = tid & 31, w = tid >> 5;
    const int qr = lane >> 2, qc = lane & 3;
    const int rm = w * 16 + qr;

    // K-fragment ldmatrix.x4 lane base: mats 0,1 <- KH (cols k, k+8), mats 2,3 <- KL
    const uint32_t kfragBase = smemB + (uint32_t)((lane >> 4) * 9216)
                             + (uint32_t)(((lane & 7) * 72 + ((lane >> 3) & 1) * 8) * 2);
    // V-fragment ldmatrix.x4.trans lane base: mats 0,1 <- VH rows k..k+15, mats 2,3 <- VL
    const uint32_t vfragBase = smemB + 18432u + (uint32_t)((lane >> 4) * 9216)
                             + (uint32_t)((lane & 15) * 144);

    const size_t hoff = (size_t)h * DHEAD;
    const size_t rowQ0 = (size_t)b * SEQ + (size_t)qb * 64;

    // ---- Q fragments (bf16 hi/lo), one-time from gmem ----
    unsigned qhi[4][4], qlo[4][4];
    {
        const float* qp = Q + rowQ0 * DMODEL + hoff;
        #pragma unroll
        for (int ks = 0; ks < 4; ks++) {
            int k = ks * 16;
            float2 t;
            t = *(const float2*)(qp + (size_t)rm * DMODEL + k + 2 * qc);
            bfsplit2(t.x, t.y, qhi[ks][0], qlo[ks][0]);
            t = *(const float2*)(qp + (size_t)(rm + 8) * DMODEL + k + 2 * qc);
            bfsplit2(t.x, t.y, qhi[ks][1], qlo[ks][1]);
            t = *(const float2*)(qp + (size_t)rm * DMODEL + k + 8 + 2 * qc);
            bfsplit2(t.x, t.y, qhi[ks][2], qlo[ks][2]);
            t = *(const float2*)(qp + (size_t)(rm + 8) * DMODEL + k + 8 + 2 * qc);
            bfsplit2(t.x, t.y, qhi[ks][3], qlo[ks][3]);
        }
    }

    float o[8][4];
    #pragma unroll
    for (int nt = 0; nt < 8; nt++)
        #pragma unroll
        for (int i = 0; i < 4; i++) o[nt][i] = 0.f;
    float m0 = -3.0e38f, m1 = -3.0e38f, l0 = 0.f, l1 = 0.f;

    const int rowg0 = qb * 64 + rm;
    const int rowg1 = rowg0 + 8;

    for (int kj = 0; kj <= qb; kj++) {
        // ---- stage K/V (64 tokens): fp32 loads + inline split ----
        const float* kp = K + ((size_t)b * SEQ + (size_t)kj * 64) * DMODEL + hoff;
        const float* vp = V + ((size_t)b * SEQ + (size_t)kj * 64) * DMODEL + hoff;
        #pragma unroll
        for (int l = 0; l < 8; l++) {
            int idx = tid + l * 128;
            int r = idx >> 4, c = (idx & 15) << 2;
            float4 kv = *(const float4*)(kp + (size_t)r * DMODEL + c);
            unsigned hA, lA, hB, lB;
            bfsplit2(kv.x, kv.y, hA, lA);
            bfsplit2(kv.z, kv.w, hB, lB);
            *(unsigned*)(KH + r * 72 + c)     = hA;
            *(unsigned*)(KH + r * 72 + c + 2) = hB;
            *(unsigned*)(KL + r * 72 + c)     = lA;
            *(unsigned*)(KL + r * 72 + c + 2) = lB;
            float4 vv = *(const float4*)(vp + (size_t)r * DMODEL + c);
            bfsplit2(vv.x, vv.y, hA, lA);
            bfsplit2(vv.z, vv.w, hB, lB);
            *(unsigned*)(VH + r * 72 + c)     = hA;
            *(unsigned*)(VH + r * 72 + c + 2) = hB;
            *(unsigned*)(VL + r * 72 + c)     = lA;
            *(unsigned*)(VL + r * 72 + c + 2) = lB;
        }
        __syncthreads();

        // ---- S = Q K^T (3-term bf16, K frags via single ldmatrix.x4) ----
        float s[8][4];
        #pragma unroll
        for (int nt = 0; nt < 8; nt++)
            #pragma unroll
            for (int i = 0; i < 4; i++) s[nt][i] = 0.f;

        #pragma unroll
        for (int ks = 0; ks < 4; ks++) {
            const int k = ks * 16;
            #pragma unroll
            for (int nt = 0; nt < 8; nt++) {
                unsigned bh[2], bl[2];
                ldmx4(bh[0], bh[1], bl[0], bl[1],
                      kfragBase + (uint32_t)(nt * 1152 + k * 2));
                mma_bf16(s[nt], qhi[ks], bh);
                mma_bf16(s[nt], qhi[ks], bl);
                mma_bf16(s[nt], qlo[ks], bh);
            }
        }

        // ---- scale + causal mask + row max ----
        float mx0 = m0, mx1 = m1;
        #pragma unroll
        for (int nt = 0; nt < 8; nt++) {
            int cg = kj * 64 + nt * 8 + 2 * qc;
            #pragma unroll
            for (int d = 0; d < 2; d++) {
                float v0 = s[nt][d] * 0.125f;
                if (cg + d > rowg0) v0 = -1e30f;
                s[nt][d] = v0; mx0 = fmaxf(mx0, v0);
                float v1 = s[nt][2 + d] * 0.125f;
                if (cg + d > rowg1) v1 = -1e30f;
                s[nt][2 + d] = v1; mx1 = fmaxf(mx1, v1);
            }
        }
        mx0 = fmaxf(mx0, __shfl_xor_sync(0xffffffffu, mx0, 1));
        mx0 = fmaxf(mx0, __shfl_xor_sync(0xffffffffu, mx0, 2));
        mx1 = fmaxf(mx1, __shfl_xor_sync(0xffffffffu, mx1, 1));
        mx1 = fmaxf(mx1, __shfl_xor_sync(0xffffffffu, mx1, 2));

        float a0 = __expf(m0 - mx0);
        float a1 = __expf(m1 - mx1);
        m0 = mx0; m1 = mx1;

        // ---- softmax + pack P fragments in registers (s layout == A-frag) ----
        unsigned phi[4][4], plo[4][4];
        float rs0 = 0.f, rs1 = 0.f;
        #pragma unroll
        for (int nt = 0; nt < 8; nt++) {
            float p0 = __expf(s[nt][0] - mx0), p1 = __expf(s[nt][1] - mx0);
            float p2 = __expf(s[nt][2] - mx1), p3 = __expf(s[nt][3] - mx1);
            rs0 += p0 + p1; rs1 += p2 + p3;
            int ks = nt >> 1, e = (nt & 1) * 2;
            bfsplit2(p0, p1, phi[ks][e],     plo[ks][e]);
            bfsplit2(p2, p3, phi[ks][e + 1], plo[ks][e + 1]);
        }
        rs0 += __shfl_xor_sync(0xffffffffu, rs0, 1);
        rs0 += __shfl_xor_sync(0xffffffffu, rs0, 2);
        rs1 += __shfl_xor_sync(0xffffffffu, rs1, 1);
        rs1 += __shfl_xor_sync(0xffffffffu, rs1, 2);
        l0 = l0 * a0 + rs0;
        l1 = l1 * a1 + rs1;

        #pragma unroll
        for (int nt = 0; nt < 8; nt++) {
            o[nt][0] *= a0; o[nt][1] *= a0;
            o[nt][2] *= a1; o[nt][3] *= a1;
        }

        // ---- O += P V (V frags via single ldmatrix.x4.trans) ----
        #pragma unroll
        for (int ks = 0; ks < 4; ks++) {
            const int k = ks * 16;
            #pragma unroll
            for (int nt = 0; nt < 8; nt++) {
                unsigned bh[2], bl[2];
                ldmx4t(bh[0], bh[1], bl[0], bl[1],
                       vfragBase + (uint32_t)(k * 144 + nt * 16));
                mma_bf16(o[nt], phi[ks], bh);
                mma_bf16(o[nt], phi[ks], bl);
                mma_bf16(o[nt], plo[ks], bh);
            }
        }
        __syncthreads();   // K/V reads done before next tile staging
    }

    // ---- normalize + write O, pre-rounded to tf32 for the Wo GEMM ----
    float inv0 = 1.0f / l0, inv1 = 1.0f / l1;
    float* op = O + rowQ0 * DMODEL + hoff;
    #pragma unroll
    for (int nt = 0; nt < 8; nt++) {
        int c = nt * 8 + 2 * qc;
        *(float2*)(op + (size_t)rm * DMODEL + c) =
            make_float2(tf32r(o[nt][0] * inv0), tf32r(o[nt][1] * inv0));
        *(float2*)(op + (size_t)(rm + 8) * DMODEL + c) =
            make_float2(tf32r(o[nt][2] * inv1), tf32r(o[nt][3] * inv1));
    }
}

// ---------------------------------------------------------------------------
// Launch
// ---------------------------------------------------------------------------
extern "C" void kernel_launch(void* const* d_in, const int* in_sizes, int n_in,
                              void* d_out, int out_size)
{
    const float* hidden = (const float*)d_in[0];
    const float* cosT   = (const float*)d_in[1];
    const float* sinT   = (const float*)d_in[2];
    // d_in[3] = attention_mask (pure causal; reproduced analytically)
    const float* Wq     = (const float*)d_in[4];
    const float* Wk     = (const float*)d_in[5];
    const float* Wv     = (const float*)d_in[6];
    const float* Wo     = (const float*)d_in[7];
    float* out = (float*)d_out;

    float *Ap, *Qp, *Kp, *Vp, *Op, *WTp, *WoTp;
    cudaGetSymbolAddress((void**)&Ap,  g_A);
    cudaGetSymbolAddress((void**)&Qp,  g_Q);
    cudaGetSymbolAddress((void**)&Kp,  g_K);
    cudaGetSymbolAddress((void**)&Vp,  g_V);
    cudaGetSymbolAddress((void**)&Op,  g_O);
    cudaGetSymbolAddress((void**)&WTp, g_WT);
    cudaGetSymbolAddress((void**)&WoTp, g_WoT);

    cudaFuncSetAttribute(gemm_ldm<true>,  cudaFuncAttributeMaxDynamicSharedMemorySize, GEMM_SMEM);
    cudaFuncSetAttribute(gemm_ldm<false>, cudaFuncAttributeMaxDynamicSharedMemorySize, GEMM_SMEM);
    cudaFuncSetAttribute(attn_mma,        cudaFuncAttributeMaxDynamicSharedMemorySize, ATTN_SMEM);

    prep_round<<<NELEM / 4 / 256, 256>>>(hidden, Ap);
    prep_weights<<<dim3(32, 32, 4), dim3(32, 8)>>>(Wq, Wk, Wv, Wo, WTp, WoTp);

    gemm_ldm<true><<<dim3(24, 32), 256, GEMM_SMEM>>>(
        Ap, WTp, nullptr, Qp, Kp, Vp, MTOT, 3072, 1024);

    rope_kernel<<<(MTOT * NHEADS * 32) / 256, 256>>>(Qp, Kp, cosT, sinT);

    attn_mma<<<dim3(SEQ / 64, NHEADS, BATCH), 128, ATTN_SMEM>>>(Qp, Kp, Vp, Op);

    gemm_ldm<false><<<dim3(8, 32), 256, GEMM_SMEM>>>(
        Op, WoTp, out, nullptr, nullptr, nullptr, MTOT, 1024, 1024);
}